// round 10
// baseline (speedup 1.0000x reference)
#include <cuda_runtime.h>
#include <math.h>
#include <stdint.h>

// ---------------------------------------------------------------------------
// Problem constants
// ---------------------------------------------------------------------------
#define B_ 2
#define T_ 8192
#define H_ 16
#define NB_ 32
#define CH 512              // H*NB
#define D_ 1024
#define DH_ 128
#define M_ (B_*T_)          // 16384 rows
#define LCH 64              // scan chunk length
#define NCHUNK (T_/LCH)     // 128 chunks

#define PI_F   3.14159265358979323846f
#define TWOPI_F 6.283185307179586f

typedef unsigned long long u64;

// ---------------------------------------------------------------------------
// Scratch (static device globals; no runtime alloc)
// ---------------------------------------------------------------------------
__device__ float g_hid[(size_t)M_*DH_];         // 8 MB
__device__ float g_nu [(size_t)M_*CH];          // 33.5 MB
__device__ float g_K[CH];
__device__ float g_alpha[CH];
__device__ float g_carry[B_*NCHUNK*CH];         // 512 KB

// ---------------------------------------------------------------------------
// Packed dual-fp32 FMA (FFMA2): two independent RN fp32 FMAs, bit-identical
// to scalar fmaf per half.
// ---------------------------------------------------------------------------
__device__ __forceinline__ void ffma2(u64& acc, u64 a, u64 b) {
    asm("fma.rn.f32x2 %0, %1, %2, %0;" : "+l"(acc) : "l"(a), "l"(b));
}
__device__ __forceinline__ float lo32(u64 v) {
    return __uint_as_float((uint32_t)v);
}
__device__ __forceinline__ float hi32(u64 v) {
    return __uint_as_float((uint32_t)(v >> 32));
}

// ---------------------------------------------------------------------------
// FFMA2 GEMM: BM=128, BN=128, BK=8, 512 threads, 4x8 micro-tile.
//   EPI==0: g_hid = gelu(A @ W1 + b1)                      KDIM=1024, NW=128
//   EPI==1: g_nu  = wrap(pi*tanh(g_hid @ W2 + b2) - theta) KDIM=128,  NW=512
// A staged DUPLICATED k-major: As[k][2m] = As[k][2m+1] = A[m][k], so one
// LDS.128 yields two broadcast u64 pairs {a,a} with no MOVs.
// B staged n-major: one LDS.128 yields two column pairs {b_n, b_{n+1}}.
// Per kk-step: 2 LDS.128 (A) + 2 LDS.128 (B) + 16 FFMA2, no packing.
// Ping-pong double buffer, register prefetch, one __syncthreads per tile.
// Thread (tx=tid&15, ty=tid>>4): rows ty*4..+3, cols {tx*4..+3, tx*4+64..+67}.
// ---------------------------------------------------------------------------
template<int KDIM, int NW, int EPI>
__global__ __launch_bounds__(512, 1) void gemm_ffma2_kernel(
    const float* __restrict__ Ain, const float* __restrict__ W,
    const float* __restrict__ bias, const float* __restrict__ theta)
{
    __shared__ float As[2][8][260];   // [buf][k][2m dup], stride 260 (pad)
    __shared__ float Bs[2][8][132];   // [buf][k][n], stride 132 (pad)

    const int tid = threadIdx.x;
    const int tx = tid & 15;
    const int ty = tid >> 4;          // 0..31
    const int m0 = blockIdx.x * 128;
    const int n0 = blockIdx.y * 128;
    constexpr int NC = KDIM / 8;

    const float* A = (EPI == 0) ? Ain : (const float*)g_hid;

    // A load: one float2 per thread.  arow = tid>>2 (0..127), akd = (tid&3)*2
    const int arow = tid >> 2;
    const int akd  = (tid & 3) * 2;
    // B load: one float2 per thread.  bkr = tid>>6 (0..7), bnc = (tid&63)*2
    const int bkr = tid >> 6;
    const int bnc = (tid & 63) * 2;

    const float* Ap = A + (size_t)(m0 + arow) * KDIM + akd;
    const float* Wp = W + (size_t)bkr * NW + n0 + bnc;

    u64 acc[4][4];
    #pragma unroll
    for (int i = 0; i < 4; i++)
        #pragma unroll
        for (int j = 0; j < 4; j++) acc[i][j] = 0ull;

    // ---- stage tile 0 ----
    float2 pa = *(const float2*)(Ap);
    float2 pb = *(const float2*)(Wp);
    {
        *(float2*)&As[0][akd + 0][2 * arow] = make_float2(pa.x, pa.x);
        *(float2*)&As[0][akd + 1][2 * arow] = make_float2(pa.y, pa.y);
        *(float2*)&Bs[0][bkr][bnc] = pb;
    }
    __syncthreads();

    int bi = 0;
    for (int c = 0; c < NC; c++) {
        // prefetch next tile into registers
        if (c + 1 < NC) {
            const int ko = (c + 1) * 8;
            pa = *(const float2*)(Ap + ko);
            pb = *(const float2*)(Wp + (size_t)ko * NW);
        }

        // compute on buffer bi
        #pragma unroll
        for (int kk = 0; kk < 8; kk++) {
            ulonglong2 ad0 = *(const ulonglong2*)&As[bi][kk][ty * 8];      // rows r0,r1
            ulonglong2 ad1 = *(const ulonglong2*)&As[bi][kk][ty * 8 + 4];  // rows r2,r3
            ulonglong2 bp0 = *(const ulonglong2*)&Bs[bi][kk][tx * 4];      // cols n0..n3
            ulonglong2 bp1 = *(const ulonglong2*)&Bs[bi][kk][tx * 4 + 64]; // cols n64..n67
            ffma2(acc[0][0], ad0.x, bp0.x); ffma2(acc[0][1], ad0.x, bp0.y);
            ffma2(acc[0][2], ad0.x, bp1.x); ffma2(acc[0][3], ad0.x, bp1.y);
            ffma2(acc[1][0], ad0.y, bp0.x); ffma2(acc[1][1], ad0.y, bp0.y);
            ffma2(acc[1][2], ad0.y, bp1.x); ffma2(acc[1][3], ad0.y, bp1.y);
            ffma2(acc[2][0], ad1.x, bp0.x); ffma2(acc[2][1], ad1.x, bp0.y);
            ffma2(acc[2][2], ad1.x, bp1.x); ffma2(acc[2][3], ad1.x, bp1.y);
            ffma2(acc[3][0], ad1.y, bp0.x); ffma2(acc[3][1], ad1.y, bp0.y);
            ffma2(acc[3][2], ad1.y, bp1.x); ffma2(acc[3][3], ad1.y, bp1.y);
        }

        // store next tile into the other buffer
        if (c + 1 < NC) {
            const int nb = bi ^ 1;
            *(float2*)&As[nb][akd + 0][2 * arow] = make_float2(pa.x, pa.x);
            *(float2*)&As[nb][akd + 1][2 * arow] = make_float2(pa.y, pa.y);
            *(float2*)&Bs[nb][bkr][bnc] = pb;
        }
        __syncthreads();
        bi ^= 1;
    }

    // ---- epilogue ----
    float4 bv0 = *(const float4*)&bias[n0 + tx * 4];
    float4 bv1 = *(const float4*)&bias[n0 + tx * 4 + 64];

    #pragma unroll
    for (int i = 0; i < 4; i++) {
        const int m = m0 + ty * 4 + i;
        #pragma unroll
        for (int g = 0; g < 2; g++) {
            const int n = n0 + tx * 4 + g * 64;
            const float4 bg = g ? bv1 : bv0;
            float4 v;
            v.x = lo32(acc[i][2 * g]);     v.y = hi32(acc[i][2 * g]);
            v.z = lo32(acc[i][2 * g + 1]); v.w = hi32(acc[i][2 * g + 1]);
            if (EPI == 0) {
                float x0 = v.x + bg.x, x1 = v.y + bg.y;
                float x2 = v.z + bg.z, x3 = v.w + bg.w;
                float4 r;
                r.x = x0 * normcdff(x0); r.y = x1 * normcdff(x1);
                r.z = x2 * normcdff(x2); r.w = x3 * normcdff(x3);
                *(float4*)&g_hid[(size_t)m * DH_ + n] = r;
            } else {
                float4 th = *(const float4*)&theta[(size_t)m * CH + n];
                float4 r;
                r.x = remainderf(PI_F * tanhf(v.x + bg.x) - th.x, TWOPI_F);
                r.y = remainderf(PI_F * tanhf(v.y + bg.y) - th.y, TWOPI_F);
                r.z = remainderf(PI_F * tanhf(v.z + bg.z) - th.z, TWOPI_F);
                r.w = remainderf(PI_F * tanhf(v.w + bg.w) - th.w, TWOPI_F);
                *(float4*)&g_nu[(size_t)m * CH + n] = r;
            }
        }
    }
}

// ---------------------------------------------------------------------------
// K* closed-form DARE
// ---------------------------------------------------------------------------
__global__ void kstar_kernel(const float* __restrict__ lq,
                             const float* __restrict__ lr,
                             float* __restrict__ outK, int write_out)
{
    int i = threadIdx.x;
    float Q = expf(lq[i]);
    float R = expf(lr[i]);
    float P_post = 0.5f * (-Q + sqrtf(Q * Q + 4.0f * Q * R));
    float P_pred = P_post + Q;
    float K = P_pred / (P_pred + R);
    g_K[i] = K;
    g_alpha[i] = 1.0f - K;
    if (write_out) outK[i] = K;
}

// ---------------------------------------------------------------------------
// Scan pass A: per-(b, chunk) local carries.  grid = B*NCHUNK, block 512.
// ---------------------------------------------------------------------------
__global__ __launch_bounds__(512) void carry_kernel()
{
    const int bx = blockIdx.x;
    const int b = bx / NCHUNK;
    const int j = bx % NCHUNK;
    const int ch = threadIdx.x;
    const float K = g_K[ch];
    const float a = g_alpha[ch];
    const float* nu = g_nu + ((size_t)(b * T_ + j * LCH)) * CH + ch;

    float c = 0.f;
    for (int i0 = 0; i0 < LCH; i0 += 8) {
        float v[8];
        #pragma unroll
        for (int u = 0; u < 8; u++) v[u] = nu[(size_t)(i0 + u) * CH];
        #pragma unroll
        for (int u = 0; u < 8; u++) c = fmaf(a, c, K * v[u]);
    }
    g_carry[(b * NCHUNK + j) * CH + ch] = c;
}

// ---------------------------------------------------------------------------
// Scan pass B: exact carry combine across chunks (factor alpha^LCH).
// ---------------------------------------------------------------------------
__global__ __launch_bounds__(512) void combine_kernel()
{
    const int b = blockIdx.x;
    const int ch = threadIdx.x;
    float a = g_alpha[ch];
    float aL = a;
    #pragma unroll
    for (int i = 0; i < 6; i++) aL *= aL;   // alpha^64

    float s = 0.f;
    for (int j0 = 0; j0 < NCHUNK; j0 += 8) {
        float v[8];
        #pragma unroll
        for (int u = 0; u < 8; u++)
            v[u] = g_carry[(b * NCHUNK + j0 + u) * CH + ch];
        #pragma unroll
        for (int u = 0; u < 8; u++) {
            g_carry[(b * NCHUNK + j0 + u) * CH + ch] = s;
            s = fmaf(aL, s, v[u]);
        }
    }
}

// ---------------------------------------------------------------------------
// Scan pass C: final recurrence; write theta_hat and d.  8-wide batches.
// ---------------------------------------------------------------------------
__global__ __launch_bounds__(512) void final_kernel(
    const float* __restrict__ theta, float* __restrict__ out, int write_d)
{
    const int bx = blockIdx.x;
    const int b = bx / NCHUNK;
    const int j = bx % NCHUNK;
    const int ch = threadIdx.x;
    const float K = g_K[ch];
    const float a = g_alpha[ch];

    float d = g_carry[(b * NCHUNK + j) * CH + ch];
    const size_t base = ((size_t)(b * T_ + j * LCH)) * CH + ch;
    float* outd = out + (size_t)M_ * CH;

    for (int i0 = 0; i0 < LCH; i0 += 8) {
        float v[8], th[8];
        #pragma unroll
        for (int u = 0; u < 8; u++) {
            const size_t idx = base + (size_t)(i0 + u) * CH;
            v[u]  = g_nu[idx];
            th[u] = theta[idx];
        }
        #pragma unroll
        for (int u = 0; u < 8; u++) {
            const size_t idx = base + (size_t)(i0 + u) * CH;
            d = fmaf(a, d, K * v[u]);
            out[idx] = th[u] + d;
            if (write_d) outd[idx] = d;
        }
    }
}

// ---------------------------------------------------------------------------
// Launch.  Inputs: theta_path, content_emb, W1, b1, W2, b2, log_Q, log_R
// Output: concat[ theta_hat (M*CH), d (M*CH), K_star (CH) ] fp32
// ---------------------------------------------------------------------------
extern "C" void kernel_launch(void* const* d_in, const int* in_sizes, int n_in,
                              void* d_out, int out_size)
{
    const float* theta = (const float*)d_in[0];
    const float* x     = (const float*)d_in[1];
    const float* W1    = (const float*)d_in[2];
    const float* b1    = (const float*)d_in[3];
    const float* W2    = (const float*)d_in[4];
    const float* b2    = (const float*)d_in[5];
    const float* lq    = (const float*)d_in[6];
    const float* lr    = (const float*)d_in[7];
    float* out = (float*)d_out;

    const size_t n_main = (size_t)M_ * CH;
    const int write_d = (size_t)out_size >= 2 * n_main;
    const int write_k = (size_t)out_size >= 2 * n_main + CH;

    kstar_kernel<<<1, CH>>>(lq, lr, out + 2 * n_main, write_k);
    gemm_ffma2_kernel<1024, DH_, 0><<<dim3(M_ / 128, 1), 512>>>(x, W1, b1, nullptr);
    gemm_ffma2_kernel<128,  CH,  1><<<dim3(M_ / 128, CH / 128), 512>>>(nullptr, W2, b2, theta);
    carry_kernel<<<B_ * NCHUNK, CH>>>();
    combine_kernel<<<B_, CH>>>();
    final_kernel<<<B_ * NCHUNK, CH>>>(theta, out, write_d);
}